// round 1
// baseline (speedup 1.0000x reference)
#include <cuda_runtime.h>
#include <math.h>

#define NTHREADS 128

static __device__ __forceinline__ float seluf(float x) {
    const float lam    = 1.0507009873554805f;
    const float lamalp = 1.0507009873554805f * 1.6732632423543772f;
    return x > 0.0f ? lam * x : lamalp * expm1f(x);
}

static __device__ __forceinline__ float softplusf(float x) {
    // matches jax.nn.softplus = logaddexp(x, 0)
    return fmaxf(x, 0.0f) + log1pf(expf(-fabsf(x)));
}

__global__ void __launch_bounds__(NTHREADS)
tetshade_kernel(
    const float*  __restrict__ vertices,   // (V,3)
    const int4*   __restrict__ indices,    // (T,4)
    const float*  __restrict__ camera,     // (3,)
    const float4* __restrict__ tables4,    // (L, 65536, 4) as float4
    const float*  __restrict__ W1, const float* __restrict__ B1,
    const float*  __restrict__ W2, const float* __restrict__ B2,
    const float*  __restrict__ W3, const float* __restrict__ B3,
    const float*  __restrict__ centerp,    // (1,3)
    const float*  __restrict__ scalep,     // scalar
    float*        __restrict__ outp,       // (T,3)
    int T)
{
    __shared__ __align__(16) float sW1[40 * 64];
    __shared__ __align__(16) float sW2[64 * 64];
    __shared__ __align__(16) float sW3[64 * 16];
    __shared__ __align__(16) float sB1[64];
    __shared__ __align__(16) float sB2[64];
    __shared__ __align__(16) float sB3[16];

    for (int i = threadIdx.x; i < 40 * 64; i += NTHREADS) sW1[i] = W1[i];
    for (int i = threadIdx.x; i < 64 * 64; i += NTHREADS) sW2[i] = W2[i];
    for (int i = threadIdx.x; i < 64 * 16; i += NTHREADS) sW3[i] = W3[i];
    if (threadIdx.x < 64) {
        sB1[threadIdx.x] = B1[threadIdx.x];
        sB2[threadIdx.x] = B2[threadIdx.x];
    }
    if (threadIdx.x < 16) sB3[threadIdx.x] = B3[threadIdx.x];
    __syncthreads();

    int t = blockIdx.x * NTHREADS + threadIdx.x;
    if (t >= T) return;

    const float EPSF = 1.1920928955078125e-07f;  // np.finfo(float32).eps

    // ---------------- gather tet vertices ----------------
    int4 id = indices[t];
    float v0x = __ldg(vertices + 3 * id.x + 0);
    float v0y = __ldg(vertices + 3 * id.x + 1);
    float v0z = __ldg(vertices + 3 * id.x + 2);
    float v1x = __ldg(vertices + 3 * id.y + 0);
    float v1y = __ldg(vertices + 3 * id.y + 1);
    float v1z = __ldg(vertices + 3 * id.y + 2);
    float v2x = __ldg(vertices + 3 * id.z + 0);
    float v2y = __ldg(vertices + 3 * id.z + 1);
    float v2z = __ldg(vertices + 3 * id.z + 2);
    float v3x = __ldg(vertices + 3 * id.w + 0);
    float v3y = __ldg(vertices + 3 * id.w + 1);
    float v3z = __ldg(vertices + 3 * id.w + 2);

    // ---------------- view direction (from barycenter) ----------------
    float bx = 0.25f * (v0x + v1x + v2x + v3x);
    float by = 0.25f * (v0y + v1y + v2y + v3y);
    float bz = 0.25f * (v0z + v1z + v2z + v3z);
    float vdx = __ldg(camera + 0) - bx;
    float vdy = __ldg(camera + 1) - by;
    float vdz = __ldg(camera + 2) - bz;
    {
        float vn = fmaxf(sqrtf(vdx * vdx + vdy * vdy + vdz * vdz), EPSF);
        vdx /= vn; vdy /= vn; vdz /= vn;
    }

    // ---------------- circumcenter: solve A cc = rhs ----------------
    float a00 = 2.0f * (v1x - v0x) + 1e-6f;
    float a01 = 2.0f * (v1y - v0y);
    float a02 = 2.0f * (v1z - v0z);
    float a10 = 2.0f * (v2x - v0x);
    float a11 = 2.0f * (v2y - v0y) + 1e-6f;
    float a12 = 2.0f * (v2z - v0z);
    float a20 = 2.0f * (v3x - v0x);
    float a21 = 2.0f * (v3y - v0y);
    float a22 = 2.0f * (v3z - v0z) + 1e-6f;
    float r0 = (v1x * v1x - v0x * v0x) + (v1y * v1y - v0y * v0y) + (v1z * v1z - v0z * v0z);
    float r1 = (v2x * v2x - v0x * v0x) + (v2y * v2y - v0y * v0y) + (v2z * v2z - v0z * v0z);
    float r2 = (v3x * v3x - v0x * v0x) + (v3y * v3y - v0y * v0y) + (v3z * v3z - v0z * v0z);

    // partial-pivot LU, 3x3 (scalar-register, branchy swaps)
    {
        float tmp;
        float m0 = fabsf(a00), m1a = fabsf(a10), m2a = fabsf(a20);
        if (m1a > m0 && m1a >= m2a) {
            tmp = a00; a00 = a10; a10 = tmp;
            tmp = a01; a01 = a11; a11 = tmp;
            tmp = a02; a02 = a12; a12 = tmp;
            tmp = r0;  r0  = r1;  r1  = tmp;
        } else if (m2a > m0) {
            tmp = a00; a00 = a20; a20 = tmp;
            tmp = a01; a01 = a21; a21 = tmp;
            tmp = a02; a02 = a22; a22 = tmp;
            tmp = r0;  r0  = r2;  r2  = tmp;
        }
        float f1 = a10 / a00, f2 = a20 / a00;
        a11 -= f1 * a01; a12 -= f1 * a02; r1 -= f1 * r0;
        a21 -= f2 * a01; a22 -= f2 * a02; r2 -= f2 * r0;
        if (fabsf(a21) > fabsf(a11)) {
            tmp = a11; a11 = a21; a21 = tmp;
            tmp = a12; a12 = a22; a22 = tmp;
            tmp = r1;  r1  = r2;  r2  = tmp;
        }
        float f3 = a21 / a11;
        a22 -= f3 * a12; r2 -= f3 * r1;
    }
    float ccz = r2 / a22;
    float ccy = (r1 - a12 * ccz) / a11;
    float ccx = (r0 - a01 * ccy - a02 * ccz) / a00;

    float radius = sqrtf((ccx - v0x) * (ccx - v0x) +
                         (ccy - v0y) * (ccy - v0y) +
                         (ccz - v0z) * (ccz - v0z));

    // ---------------- ball contraction ----------------
    float ss  = __ldg(scalep);
    float nx  = (ccx - __ldg(centerp + 0)) / ss;
    float ny  = (ccy - __ldg(centerp + 1)) / ss;
    float nz  = (ccz - __ldg(centerp + 2)) / ss;
    float n   = fmaxf(sqrtf(nx * nx + ny * ny + nz * nz), EPSF);
    float cvx, cvy, cvz, fac;
    if (n <= 1.0f) {
        cvx = nx; cvy = ny; cvz = nz; fac = 1.0f;
    } else {
        float inv = 1.0f / n;
        float s2  = (2.0f - inv) * inv;
        cvx = nx * s2; cvy = ny * s2; cvz = nz * s2;
        fac = inv * inv;
    }
    float cr = radius / ss * fac * 0.5f;

    float hx = cvx * 0.25f + 0.5f;
    float hy = cvy * 0.25f + 0.5f;
    float hz = cvz * 0.25f + 0.5f;

    // ---------------- hash-grid encode (L=10, DIM=4) ----------------
    float xin[40];
#pragma unroll
    for (int l = 0; l < 10; ++l) {
        float resf = (float)(16 << l);
        float px = hx * resf, py = hy * resf, pz = hz * resf;
        float fx = floorf(px), fy = floorf(py), fz = floorf(pz);
        float wx = px - fx, wy = py - fy, wz = pz - fz;
        unsigned ux = (unsigned)(int)fx;
        unsigned uy = (unsigned)(int)fy;
        unsigned uz = (unsigned)(int)fz;
        unsigned ux1 = ux + 1u;
        unsigned hy0 = uy * 2654435761u, hy1 = (uy + 1u) * 2654435761u;
        unsigned hz0 = uz * 805459861u,  hz1 = (uz + 1u) * 805459861u;
        float wx0 = 1.0f - wx, wy0 = 1.0f - wy, wz0 = 1.0f - wz;
        const float4* tl = tables4 + ((size_t)l << 16);
        float ax = 0.0f, ay = 0.0f, az = 0.0f, aw = 0.0f;
        {
            float4 c = __ldg(tl + ((ux  ^ hy0 ^ hz0) & 0xFFFFu)); float w = wx0 * wy0 * wz0;
            ax = fmaf(w, c.x, ax); ay = fmaf(w, c.y, ay); az = fmaf(w, c.z, az); aw = fmaf(w, c.w, aw);
        }
        {
            float4 c = __ldg(tl + ((ux  ^ hy0 ^ hz1) & 0xFFFFu)); float w = wx0 * wy0 * wz;
            ax = fmaf(w, c.x, ax); ay = fmaf(w, c.y, ay); az = fmaf(w, c.z, az); aw = fmaf(w, c.w, aw);
        }
        {
            float4 c = __ldg(tl + ((ux  ^ hy1 ^ hz0) & 0xFFFFu)); float w = wx0 * wy * wz0;
            ax = fmaf(w, c.x, ax); ay = fmaf(w, c.y, ay); az = fmaf(w, c.z, az); aw = fmaf(w, c.w, aw);
        }
        {
            float4 c = __ldg(tl + ((ux  ^ hy1 ^ hz1) & 0xFFFFu)); float w = wx0 * wy * wz;
            ax = fmaf(w, c.x, ax); ay = fmaf(w, c.y, ay); az = fmaf(w, c.z, az); aw = fmaf(w, c.w, aw);
        }
        {
            float4 c = __ldg(tl + ((ux1 ^ hy0 ^ hz0) & 0xFFFFu)); float w = wx * wy0 * wz0;
            ax = fmaf(w, c.x, ax); ay = fmaf(w, c.y, ay); az = fmaf(w, c.z, az); aw = fmaf(w, c.w, aw);
        }
        {
            float4 c = __ldg(tl + ((ux1 ^ hy0 ^ hz1) & 0xFFFFu)); float w = wx * wy0 * wz;
            ax = fmaf(w, c.x, ax); ay = fmaf(w, c.y, ay); az = fmaf(w, c.z, az); aw = fmaf(w, c.w, aw);
        }
        {
            float4 c = __ldg(tl + ((ux1 ^ hy1 ^ hz0) & 0xFFFFu)); float w = wx * wy * wz0;
            ax = fmaf(w, c.x, ax); ay = fmaf(w, c.y, ay); az = fmaf(w, c.z, az); aw = fmaf(w, c.w, aw);
        }
        {
            float4 c = __ldg(tl + ((ux1 ^ hy1 ^ hz1) & 0xFFFFu)); float w = wx * wy * wz;
            ax = fmaf(w, c.x, ax); ay = fmaf(w, c.y, ay); az = fmaf(w, c.z, az); aw = fmaf(w, c.w, aw);
        }
        float denom = 8.0f * (float)l * cr;            // PLS*4*l*cr
        float sc = erff(rsqrtf(fmaxf(denom, EPSF)));
        xin[l]      = ax * sc;   // enc layout: i = d*10 + l
        xin[10 + l] = ay * sc;
        xin[20 + l] = az * sc;
        xin[30 + l] = aw * sc;
    }

    // ---------------- MLP: 40 -> 64 -> 64 -> 16 ----------------
    float h1[64];
#pragma unroll
    for (int j = 0; j < 16; ++j) {
        float4 acc = ((const float4*)sB1)[j];
        const float4* w4 = (const float4*)sW1;
#pragma unroll
        for (int i = 0; i < 40; ++i) {
            float4 w = w4[i * 16 + j];
            acc.x = fmaf(xin[i], w.x, acc.x);
            acc.y = fmaf(xin[i], w.y, acc.y);
            acc.z = fmaf(xin[i], w.z, acc.z);
            acc.w = fmaf(xin[i], w.w, acc.w);
        }
        h1[4 * j + 0] = seluf(acc.x);
        h1[4 * j + 1] = seluf(acc.y);
        h1[4 * j + 2] = seluf(acc.z);
        h1[4 * j + 3] = seluf(acc.w);
    }

    float h2[64];
#pragma unroll
    for (int j = 0; j < 16; ++j) {
        float4 acc = ((const float4*)sB2)[j];
        const float4* w4 = (const float4*)sW2;
#pragma unroll
        for (int i = 0; i < 64; ++i) {
            float4 w = w4[i * 16 + j];
            acc.x = fmaf(h1[i], w.x, acc.x);
            acc.y = fmaf(h1[i], w.y, acc.y);
            acc.z = fmaf(h1[i], w.z, acc.z);
            acc.w = fmaf(h1[i], w.w, acc.w);
        }
        h2[4 * j + 0] = seluf(acc.x);
        h2[4 * j + 1] = seluf(acc.y);
        h2[4 * j + 2] = seluf(acc.z);
        h2[4 * j + 3] = seluf(acc.w);
    }

    float o[16];
#pragma unroll
    for (int j = 0; j < 4; ++j) {
        float4 acc = ((const float4*)sB3)[j];
        const float4* w4 = (const float4*)sW3;
#pragma unroll
        for (int i = 0; i < 64; ++i) {
            float4 w = w4[i * 4 + j];
            acc.x = fmaf(h2[i], w.x, acc.x);
            acc.y = fmaf(h2[i], w.y, acc.y);
            acc.z = fmaf(h2[i], w.z, acc.z);
            acc.w = fmaf(h2[i], w.w, acc.w);
        }
        o[4 * j + 0] = acc.x;
        o[4 * j + 1] = acc.y;
        o[4 * j + 2] = acc.z;
        o[4 * j + 3] = acc.w;
    }

    // ---------------- lighting epilogue ----------------
    float out0 = softplusf(o[0]);
    float out1 = softplusf(o[1]);
    float out2 = softplusf(o[2]);

#pragma unroll
    for (int k = 0; k < 2; ++k) {
        const int b = 4 + 6 * k;
        float lc0 = softplusf(o[b + 0] - 3.0f);
        float lc1 = softplusf(o[b + 1] - 3.0f);
        float lc2 = softplusf(o[b + 2] - 3.0f);
        float e = o[b + 3] - 1.0f;
        e = fminf(fmaxf(e, -30.0f), 15.0f);
        float rough = 4.0f * fminf(expf(e), 100.0f);
        float rd0 = o[b + 4] + (k ? 3.14159265358979323846f : 0.0f);
        float rd1 = o[b + 5];
        float s0, c0, s1, c1;
        sincosf(rd0, &s0, &c0);
        sincosf(rd1, &s1, &c1);
        float rx = c0 * s1, ry = s0 * s1, rz = c1;
        float sim = rx * vdx + ry * vdy + rz * vdz;
        float spec = (sim > 0.0f) ? powf(fmaxf(sim, EPSF), rough) : 0.0f;
        out0 = fmaf(lc0, spec, out0);
        out1 = fmaf(lc1, spec, out1);
        out2 = fmaf(lc2, spec, out2);
    }

    outp[3 * t + 0] = out0;
    outp[3 * t + 1] = out1;
    outp[3 * t + 2] = out2;
}

extern "C" void kernel_launch(void* const* d_in, const int* in_sizes, int n_in,
                              void* d_out, int out_size)
{
    const float*  vertices = (const float*)d_in[0];
    const int4*   indices  = (const int4*)d_in[1];
    const float*  camera   = (const float*)d_in[2];
    const float4* tables   = (const float4*)d_in[3];
    const float*  W1 = (const float*)d_in[4];
    const float*  B1 = (const float*)d_in[5];
    const float*  W2 = (const float*)d_in[6];
    const float*  B2 = (const float*)d_in[7];
    const float*  W3 = (const float*)d_in[8];
    const float*  B3 = (const float*)d_in[9];
    const float*  center = (const float*)d_in[10];
    const float*  scale  = (const float*)d_in[11];

    int T = in_sizes[1] / 4;
    int grid = (T + NTHREADS - 1) / NTHREADS;
    tetshade_kernel<<<grid, NTHREADS>>>(vertices, indices, camera, tables,
                                        W1, B1, W2, B2, W3, B3,
                                        center, scale, (float*)d_out, T);
}

// round 2
// speedup vs baseline: 1.7672x; 1.7672x over previous
#include <cuda_runtime.h>
#include <math.h>

#define NTHREADS 128
typedef unsigned long long u64;

static __device__ __forceinline__ u64 pk(float lo, float hi) {
    u64 r;
    asm("mov.b64 %0, {%1, %2};" : "=l"(r) : "f"(lo), "f"(hi));
    return r;
}
static __device__ __forceinline__ float lo2(u64 v) {
    float lo, hi;
    asm("mov.b64 {%0, %1}, %2;" : "=f"(lo), "=f"(hi) : "l"(v));
    return lo;
}
static __device__ __forceinline__ float hi2(u64 v) {
    float lo, hi;
    asm("mov.b64 {%0, %1}, %2;" : "=f"(lo), "=f"(hi) : "l"(v));
    return hi;
}
static __device__ __forceinline__ u64 ffma2(u64 a, u64 b, u64 c) {
    u64 d;
    asm("fma.rn.f32x2 %0, %1, %2, %3;" : "=l"(d) : "l"(a), "l"(b), "l"(c));
    return d;
}

static __device__ __forceinline__ float seluf(float x) {
    const float lam    = 1.0507009873554805f;
    const float lamalp = 1.7580993408473766f;   // lam * alpha
    float e = __expf(x) - 1.0f;
    return x > 0.0f ? lam * x : lamalp * e;
}

static __device__ __forceinline__ float softplusf(float x) {
    return fmaxf(x, 0.0f) + log1pf(expf(-fabsf(x)));
}

__global__ void __launch_bounds__(NTHREADS, 4)
tetshade_kernel(
    const float*  __restrict__ vertices,   // (V,3)
    const int4*   __restrict__ indices,    // (T,4)
    const float*  __restrict__ camera,     // (3,)
    const float4* __restrict__ tables4,    // (L, 65536, 4)
    const float*  __restrict__ W1, const float* __restrict__ B1,
    const float*  __restrict__ W2, const float* __restrict__ B2,
    const float*  __restrict__ W3, const float* __restrict__ B3,
    const float*  __restrict__ centerp,
    const float*  __restrict__ scalep,
    float*        __restrict__ outp,
    int T)
{
    // Transposed weights: row j holds all inputs i (contiguous, 16B-aligned rows)
    __shared__ __align__(16) float sW1T[64 * 48];   // [j][i], rows padded 40->48
    __shared__ __align__(16) float sW2T[64 * 64];   // [j][i]
    __shared__ __align__(16) float sW3T[16 * 64];   // [j][i]
    __shared__ __align__(16) float sB1[64];
    __shared__ __align__(16) float sB2[64];
    __shared__ __align__(16) float sB3[16];

    for (int idx = threadIdx.x; idx < 40 * 64; idx += NTHREADS) {
        int i = idx >> 6, j = idx & 63;
        sW1T[j * 48 + i] = W1[idx];
    }
    for (int idx = threadIdx.x; idx < 64 * 64; idx += NTHREADS) {
        int i = idx >> 6, j = idx & 63;
        sW2T[j * 64 + i] = W2[idx];
    }
    for (int idx = threadIdx.x; idx < 64 * 16; idx += NTHREADS) {
        int i = idx >> 4, j = idx & 15;
        sW3T[j * 64 + i] = W3[idx];
    }
    if (threadIdx.x < 64) {
        sB1[threadIdx.x] = B1[threadIdx.x];
        sB2[threadIdx.x] = B2[threadIdx.x];
    }
    if (threadIdx.x < 16) sB3[threadIdx.x] = B3[threadIdx.x];
    __syncthreads();

    int t = blockIdx.x * NTHREADS + threadIdx.x;
    if (t >= T) return;

    const float EPSF = 1.1920928955078125e-07f;

    // ---------------- gather tet vertices ----------------
    int4 id = indices[t];
    float v0x = __ldg(vertices + 3 * id.x + 0);
    float v0y = __ldg(vertices + 3 * id.x + 1);
    float v0z = __ldg(vertices + 3 * id.x + 2);
    float v1x = __ldg(vertices + 3 * id.y + 0);
    float v1y = __ldg(vertices + 3 * id.y + 1);
    float v1z = __ldg(vertices + 3 * id.y + 2);
    float v2x = __ldg(vertices + 3 * id.z + 0);
    float v2y = __ldg(vertices + 3 * id.z + 1);
    float v2z = __ldg(vertices + 3 * id.z + 2);
    float v3x = __ldg(vertices + 3 * id.w + 0);
    float v3y = __ldg(vertices + 3 * id.w + 1);
    float v3z = __ldg(vertices + 3 * id.w + 2);

    // view direction from barycenter
    float bx = 0.25f * (v0x + v1x + v2x + v3x);
    float by = 0.25f * (v0y + v1y + v2y + v3y);
    float bz = 0.25f * (v0z + v1z + v2z + v3z);
    float vdx = __ldg(camera + 0) - bx;
    float vdy = __ldg(camera + 1) - by;
    float vdz = __ldg(camera + 2) - bz;
    {
        float vn = fmaxf(sqrtf(vdx * vdx + vdy * vdy + vdz * vdz), EPSF);
        vdx /= vn; vdy /= vn; vdz /= vn;
    }

    // ---------------- circumcenter solve ----------------
    float a00 = 2.0f * (v1x - v0x) + 1e-6f;
    float a01 = 2.0f * (v1y - v0y);
    float a02 = 2.0f * (v1z - v0z);
    float a10 = 2.0f * (v2x - v0x);
    float a11 = 2.0f * (v2y - v0y) + 1e-6f;
    float a12 = 2.0f * (v2z - v0z);
    float a20 = 2.0f * (v3x - v0x);
    float a21 = 2.0f * (v3y - v0y);
    float a22 = 2.0f * (v3z - v0z) + 1e-6f;
    float r0 = (v1x * v1x - v0x * v0x) + (v1y * v1y - v0y * v0y) + (v1z * v1z - v0z * v0z);
    float r1 = (v2x * v2x - v0x * v0x) + (v2y * v2y - v0y * v0y) + (v2z * v2z - v0z * v0z);
    float r2 = (v3x * v3x - v0x * v0x) + (v3y * v3y - v0y * v0y) + (v3z * v3z - v0z * v0z);
    {
        float tmp;
        float m0 = fabsf(a00), m1a = fabsf(a10), m2a = fabsf(a20);
        if (m1a > m0 && m1a >= m2a) {
            tmp = a00; a00 = a10; a10 = tmp;
            tmp = a01; a01 = a11; a11 = tmp;
            tmp = a02; a02 = a12; a12 = tmp;
            tmp = r0;  r0  = r1;  r1  = tmp;
        } else if (m2a > m0) {
            tmp = a00; a00 = a20; a20 = tmp;
            tmp = a01; a01 = a21; a21 = tmp;
            tmp = a02; a02 = a22; a22 = tmp;
            tmp = r0;  r0  = r2;  r2  = tmp;
        }
        float f1 = a10 / a00, f2 = a20 / a00;
        a11 -= f1 * a01; a12 -= f1 * a02; r1 -= f1 * r0;
        a21 -= f2 * a01; a22 -= f2 * a02; r2 -= f2 * r0;
        if (fabsf(a21) > fabsf(a11)) {
            tmp = a11; a11 = a21; a21 = tmp;
            tmp = a12; a12 = a22; a22 = tmp;
            tmp = r1;  r1  = r2;  r2  = tmp;
        }
        float f3 = a21 / a11;
        a22 -= f3 * a12; r2 -= f3 * r1;
    }
    float ccz = r2 / a22;
    float ccy = (r1 - a12 * ccz) / a11;
    float ccx = (r0 - a01 * ccy - a02 * ccz) / a00;

    float radius = sqrtf((ccx - v0x) * (ccx - v0x) +
                         (ccy - v0y) * (ccy - v0y) +
                         (ccz - v0z) * (ccz - v0z));

    // ---------------- ball contraction ----------------
    float ss  = __ldg(scalep);
    float nx  = (ccx - __ldg(centerp + 0)) / ss;
    float ny  = (ccy - __ldg(centerp + 1)) / ss;
    float nz  = (ccz - __ldg(centerp + 2)) / ss;
    float n   = fmaxf(sqrtf(nx * nx + ny * ny + nz * nz), EPSF);
    float cvx, cvy, cvz, fac;
    if (n <= 1.0f) {
        cvx = nx; cvy = ny; cvz = nz; fac = 1.0f;
    } else {
        float inv = 1.0f / n;
        float s2  = (2.0f - inv) * inv;
        cvx = nx * s2; cvy = ny * s2; cvz = nz * s2;
        fac = inv * inv;
    }
    float cr = radius / ss * fac * 0.5f;

    float hx = cvx * 0.25f + 0.5f;
    float hy = cvy * 0.25f + 0.5f;
    float hz = cvz * 0.25f + 0.5f;

    // ---------------- hash-grid encode ----------------
    float xin[40];
#pragma unroll
    for (int l = 0; l < 10; ++l) {
        float resf = (float)(16 << l);
        float px = hx * resf, py = hy * resf, pz = hz * resf;
        float fx = floorf(px), fy = floorf(py), fz = floorf(pz);
        float wx = px - fx, wy = py - fy, wz = pz - fz;
        unsigned ux = (unsigned)(int)fx;
        unsigned uy = (unsigned)(int)fy;
        unsigned uz = (unsigned)(int)fz;
        unsigned ux1 = ux + 1u;
        unsigned hy0 = uy * 2654435761u, hy1 = (uy + 1u) * 2654435761u;
        unsigned hz0 = uz * 805459861u,  hz1 = (uz + 1u) * 805459861u;
        float wx0 = 1.0f - wx, wy0 = 1.0f - wy, wz0 = 1.0f - wz;
        const float4* tl = tables4 + ((size_t)l << 16);
        float ax = 0.0f, ay = 0.0f, az = 0.0f, aw = 0.0f;
        {
            float4 c = __ldg(tl + ((ux  ^ hy0 ^ hz0) & 0xFFFFu)); float w = wx0 * wy0 * wz0;
            ax = fmaf(w, c.x, ax); ay = fmaf(w, c.y, ay); az = fmaf(w, c.z, az); aw = fmaf(w, c.w, aw);
        }
        {
            float4 c = __ldg(tl + ((ux  ^ hy0 ^ hz1) & 0xFFFFu)); float w = wx0 * wy0 * wz;
            ax = fmaf(w, c.x, ax); ay = fmaf(w, c.y, ay); az = fmaf(w, c.z, az); aw = fmaf(w, c.w, aw);
        }
        {
            float4 c = __ldg(tl + ((ux  ^ hy1 ^ hz0) & 0xFFFFu)); float w = wx0 * wy * wz0;
            ax = fmaf(w, c.x, ax); ay = fmaf(w, c.y, ay); az = fmaf(w, c.z, az); aw = fmaf(w, c.w, aw);
        }
        {
            float4 c = __ldg(tl + ((ux  ^ hy1 ^ hz1) & 0xFFFFu)); float w = wx0 * wy * wz;
            ax = fmaf(w, c.x, ax); ay = fmaf(w, c.y, ay); az = fmaf(w, c.z, az); aw = fmaf(w, c.w, aw);
        }
        {
            float4 c = __ldg(tl + ((ux1 ^ hy0 ^ hz0) & 0xFFFFu)); float w = wx * wy0 * wz0;
            ax = fmaf(w, c.x, ax); ay = fmaf(w, c.y, ay); az = fmaf(w, c.z, az); aw = fmaf(w, c.w, aw);
        }
        {
            float4 c = __ldg(tl + ((ux1 ^ hy0 ^ hz1) & 0xFFFFu)); float w = wx * wy0 * wz;
            ax = fmaf(w, c.x, ax); ay = fmaf(w, c.y, ay); az = fmaf(w, c.z, az); aw = fmaf(w, c.w, aw);
        }
        {
            float4 c = __ldg(tl + ((ux1 ^ hy1 ^ hz0) & 0xFFFFu)); float w = wx * wy * wz0;
            ax = fmaf(w, c.x, ax); ay = fmaf(w, c.y, ay); az = fmaf(w, c.z, az); aw = fmaf(w, c.w, aw);
        }
        {
            float4 c = __ldg(tl + ((ux1 ^ hy1 ^ hz1) & 0xFFFFu)); float w = wx * wy * wz;
            ax = fmaf(w, c.x, ax); ay = fmaf(w, c.y, ay); az = fmaf(w, c.z, az); aw = fmaf(w, c.w, aw);
        }
        float denom = 8.0f * (float)l * cr;
        float sc = erff(rsqrtf(fmaxf(denom, EPSF)));
        xin[l]      = ax * sc;
        xin[10 + l] = ay * sc;
        xin[20 + l] = az * sc;
        xin[30 + l] = aw * sc;
    }

    // pack inputs into f32x2 pairs: xinp[p] = (xin[2p], xin[2p+1])
    u64 xinp[20];
#pragma unroll
    for (int p = 0; p < 20; ++p) xinp[p] = pk(xin[2 * p], xin[2 * p + 1]);

    // ---------------- layer 1: 40 -> 64 (4 chunks of 16 outputs) ----------------
    // acc halves accumulate (even-i, odd-i) partial sums
    u64 h1p[32];
#pragma unroll
    for (int c = 0; c < 4; ++c) {
        u64 acc[16];
#pragma unroll
        for (int j = 0; j < 16; ++j) acc[j] = pk(sB1[c * 16 + j], 0.0f);
#pragma unroll
        for (int q = 0; q < 10; ++q) {          // inputs i = 4q..4q+3
#pragma unroll
            for (int j = 0; j < 16; ++j) {
                ulonglong2 w = *(const ulonglong2*)&sW1T[(c * 16 + j) * 48 + 4 * q];
                acc[j] = ffma2(xinp[2 * q],     w.x, acc[j]);
                acc[j] = ffma2(xinp[2 * q + 1], w.y, acc[j]);
            }
        }
#pragma unroll
        for (int j = 0; j < 8; ++j) {
            float a = seluf(lo2(acc[2 * j])     + hi2(acc[2 * j]));
            float b = seluf(lo2(acc[2 * j + 1]) + hi2(acc[2 * j + 1]));
            h1p[c * 8 + j] = pk(a, b);
        }
    }

    // ---------------- layer 2 (64->64) fused with layer 3 (64->16) ----------------
    u64 oacc[16];
#pragma unroll
    for (int j = 0; j < 16; ++j) oacc[j] = pk(sB3[j], 0.0f);

#pragma unroll
    for (int c = 0; c < 8; ++c) {               // 8 h2 outputs per chunk
        u64 acc[8];
#pragma unroll
        for (int j = 0; j < 8; ++j) acc[j] = pk(sB2[c * 8 + j], 0.0f);
#pragma unroll
        for (int q = 0; q < 16; ++q) {          // inputs i = 4q..4q+3
#pragma unroll
            for (int j = 0; j < 8; ++j) {
                ulonglong2 w = *(const ulonglong2*)&sW2T[(c * 8 + j) * 64 + 4 * q];
                acc[j] = ffma2(h1p[2 * q],     w.x, acc[j]);
                acc[j] = ffma2(h1p[2 * q + 1], w.y, acc[j]);
            }
        }
        u64 h2p[4];
#pragma unroll
        for (int j = 0; j < 4; ++j) {
            float a = seluf(lo2(acc[2 * j])     + hi2(acc[2 * j]));
            float b = seluf(lo2(acc[2 * j + 1]) + hi2(acc[2 * j + 1]));
            h2p[j] = pk(a, b);
        }
        // layer-3 contribution of this h2 chunk (inputs i = 8c..8c+7)
#pragma unroll
        for (int j = 0; j < 16; ++j) {
            ulonglong2 w  = *(const ulonglong2*)&sW3T[j * 64 + 8 * c];
            oacc[j] = ffma2(h2p[0], w.x, oacc[j]);
            oacc[j] = ffma2(h2p[1], w.y, oacc[j]);
            ulonglong2 w2 = *(const ulonglong2*)&sW3T[j * 64 + 8 * c + 4];
            oacc[j] = ffma2(h2p[2], w2.x, oacc[j]);
            oacc[j] = ffma2(h2p[3], w2.y, oacc[j]);
        }
    }

    float o[16];
#pragma unroll
    for (int j = 0; j < 16; ++j) o[j] = lo2(oacc[j]) + hi2(oacc[j]);

    // ---------------- lighting epilogue ----------------
    float out0 = softplusf(o[0]);
    float out1 = softplusf(o[1]);
    float out2 = softplusf(o[2]);

#pragma unroll
    for (int k = 0; k < 2; ++k) {
        const int b = 4 + 6 * k;
        float lc0 = softplusf(o[b + 0] - 3.0f);
        float lc1 = softplusf(o[b + 1] - 3.0f);
        float lc2 = softplusf(o[b + 2] - 3.0f);
        float e = o[b + 3] - 1.0f;
        e = fminf(fmaxf(e, -30.0f), 15.0f);
        float rough = 4.0f * fminf(expf(e), 100.0f);
        float rd0 = o[b + 4] + (k ? 3.14159265358979323846f : 0.0f);
        float rd1 = o[b + 5];
        float s0, c0, s1, c1;
        sincosf(rd0, &s0, &c0);
        sincosf(rd1, &s1, &c1);
        float rx = c0 * s1, ry = s0 * s1, rz = c1;
        float sim = rx * vdx + ry * vdy + rz * vdz;
        float spec = (sim > 0.0f) ? powf(fmaxf(sim, EPSF), rough) : 0.0f;
        out0 = fmaf(lc0, spec, out0);
        out1 = fmaf(lc1, spec, out1);
        out2 = fmaf(lc2, spec, out2);
    }

    outp[3 * t + 0] = out0;
    outp[3 * t + 1] = out1;
    outp[3 * t + 2] = out2;
}

extern "C" void kernel_launch(void* const* d_in, const int* in_sizes, int n_in,
                              void* d_out, int out_size)
{
    const float*  vertices = (const float*)d_in[0];
    const int4*   indices  = (const int4*)d_in[1];
    const float*  camera   = (const float*)d_in[2];
    const float4* tables   = (const float4*)d_in[3];
    const float*  W1 = (const float*)d_in[4];
    const float*  B1 = (const float*)d_in[5];
    const float*  W2 = (const float*)d_in[6];
    const float*  B2 = (const float*)d_in[7];
    const float*  W3 = (const float*)d_in[8];
    const float*  B3 = (const float*)d_in[9];
    const float*  center = (const float*)d_in[10];
    const float*  scale  = (const float*)d_in[11];

    int T = in_sizes[1] / 4;
    int grid = (T + NTHREADS - 1) / NTHREADS;
    tetshade_kernel<<<grid, NTHREADS>>>(vertices, indices, camera, tables,
                                        W1, B1, W2, B2, W3, B3,
                                        center, scale, (float*)d_out, T);
}

// round 3
// speedup vs baseline: 1.8463x; 1.0448x over previous
#include <cuda_runtime.h>
#include <math.h>

#define NTHREADS 128

__constant__ float cW1[40 * 64];
__constant__ float cB1[64];
__constant__ float cW2[64 * 64];
__constant__ float cB2[64];
__constant__ float cW3[64 * 16];
__constant__ float cB3[16];

static __device__ __forceinline__ float seluf(float x) {
    const float lam    = 1.0507009873554805f;
    const float lamalp = 1.7580993408473766f;   // lam * alpha
    float e = __expf(x) - 1.0f;
    return x > 0.0f ? lam * x : lamalp * e;
}

static __device__ __forceinline__ float softplusf(float x) {
    return fmaxf(x, 0.0f) + log1pf(expf(-fabsf(x)));
}

__global__ void __launch_bounds__(NTHREADS, 4)
tetshade_kernel(
    const float*  __restrict__ vertices,   // (V,3)
    const int4*   __restrict__ indices,    // (T,4)
    const float*  __restrict__ camera,     // (3,)
    const float4* __restrict__ tables4,    // (L, 65536, 4)
    float*        __restrict__ outp,       // (T,3)
    const float*  __restrict__ centerp,
    const float*  __restrict__ scalep,
    int T)
{
    int t = blockIdx.x * NTHREADS + threadIdx.x;
    if (t >= T) return;

    const float EPSF = 1.1920928955078125e-07f;

    // ---------------- gather tet vertices ----------------
    int4 id = indices[t];
    float v0x = __ldg(vertices + 3 * id.x + 0);
    float v0y = __ldg(vertices + 3 * id.x + 1);
    float v0z = __ldg(vertices + 3 * id.x + 2);
    float v1x = __ldg(vertices + 3 * id.y + 0);
    float v1y = __ldg(vertices + 3 * id.y + 1);
    float v1z = __ldg(vertices + 3 * id.y + 2);
    float v2x = __ldg(vertices + 3 * id.z + 0);
    float v2y = __ldg(vertices + 3 * id.z + 1);
    float v2z = __ldg(vertices + 3 * id.z + 2);
    float v3x = __ldg(vertices + 3 * id.w + 0);
    float v3y = __ldg(vertices + 3 * id.w + 1);
    float v3z = __ldg(vertices + 3 * id.w + 2);

    // view direction from barycenter
    float bx = 0.25f * (v0x + v1x + v2x + v3x);
    float by = 0.25f * (v0y + v1y + v2y + v3y);
    float bz = 0.25f * (v0z + v1z + v2z + v3z);
    float vdx = __ldg(camera + 0) - bx;
    float vdy = __ldg(camera + 1) - by;
    float vdz = __ldg(camera + 2) - bz;
    {
        float vn = fmaxf(sqrtf(vdx * vdx + vdy * vdy + vdz * vdz), EPSF);
        vdx /= vn; vdy /= vn; vdz /= vn;
    }

    // ---------------- circumcenter solve ----------------
    float a00 = 2.0f * (v1x - v0x) + 1e-6f;
    float a01 = 2.0f * (v1y - v0y);
    float a02 = 2.0f * (v1z - v0z);
    float a10 = 2.0f * (v2x - v0x);
    float a11 = 2.0f * (v2y - v0y) + 1e-6f;
    float a12 = 2.0f * (v2z - v0z);
    float a20 = 2.0f * (v3x - v0x);
    float a21 = 2.0f * (v3y - v0y);
    float a22 = 2.0f * (v3z - v0z) + 1e-6f;
    float r0 = (v1x * v1x - v0x * v0x) + (v1y * v1y - v0y * v0y) + (v1z * v1z - v0z * v0z);
    float r1 = (v2x * v2x - v0x * v0x) + (v2y * v2y - v0y * v0y) + (v2z * v2z - v0z * v0z);
    float r2 = (v3x * v3x - v0x * v0x) + (v3y * v3y - v0y * v0y) + (v3z * v3z - v0z * v0z);
    {
        float tmp;
        float m0 = fabsf(a00), m1a = fabsf(a10), m2a = fabsf(a20);
        if (m1a > m0 && m1a >= m2a) {
            tmp = a00; a00 = a10; a10 = tmp;
            tmp = a01; a01 = a11; a11 = tmp;
            tmp = a02; a02 = a12; a12 = tmp;
            tmp = r0;  r0  = r1;  r1  = tmp;
        } else if (m2a > m0) {
            tmp = a00; a00 = a20; a20 = tmp;
            tmp = a01; a01 = a21; a21 = tmp;
            tmp = a02; a02 = a22; a22 = tmp;
            tmp = r0;  r0  = r2;  r2  = tmp;
        }
        float f1 = a10 / a00, f2 = a20 / a00;
        a11 -= f1 * a01; a12 -= f1 * a02; r1 -= f1 * r0;
        a21 -= f2 * a01; a22 -= f2 * a02; r2 -= f2 * r0;
        if (fabsf(a21) > fabsf(a11)) {
            tmp = a11; a11 = a21; a21 = tmp;
            tmp = a12; a12 = a22; a22 = tmp;
            tmp = r1;  r1  = r2;  r2  = tmp;
        }
        float f3 = a21 / a11;
        a22 -= f3 * a12; r2 -= f3 * r1;
    }
    float ccz = r2 / a22;
    float ccy = (r1 - a12 * ccz) / a11;
    float ccx = (r0 - a01 * ccy - a02 * ccz) / a00;

    float radius = sqrtf((ccx - v0x) * (ccx - v0x) +
                         (ccy - v0y) * (ccy - v0y) +
                         (ccz - v0z) * (ccz - v0z));

    // ---------------- ball contraction ----------------
    float ss  = __ldg(scalep);
    float nx  = (ccx - __ldg(centerp + 0)) / ss;
    float ny  = (ccy - __ldg(centerp + 1)) / ss;
    float nz  = (ccz - __ldg(centerp + 2)) / ss;
    float n   = fmaxf(sqrtf(nx * nx + ny * ny + nz * nz), EPSF);
    float cvx, cvy, cvz, fac;
    if (n <= 1.0f) {
        cvx = nx; cvy = ny; cvz = nz; fac = 1.0f;
    } else {
        float inv = 1.0f / n;
        float s2  = (2.0f - inv) * inv;
        cvx = nx * s2; cvy = ny * s2; cvz = nz * s2;
        fac = inv * inv;
    }
    float cr = radius / ss * fac * 0.5f;

    float hx = cvx * 0.25f + 0.5f;
    float hy = cvy * 0.25f + 0.5f;
    float hz = cvz * 0.25f + 0.5f;

    // ---------------- hash-grid encode ----------------
    float xin[40];
#pragma unroll
    for (int l = 0; l < 10; ++l) {
        float resf = (float)(16 << l);
        float px = hx * resf, py = hy * resf, pz = hz * resf;
        float fx = floorf(px), fy = floorf(py), fz = floorf(pz);
        float wx = px - fx, wy = py - fy, wz = pz - fz;
        unsigned ux = (unsigned)(int)fx;
        unsigned uy = (unsigned)(int)fy;
        unsigned uz = (unsigned)(int)fz;
        unsigned ux1 = ux + 1u;
        unsigned hy0 = uy * 2654435761u, hy1 = (uy + 1u) * 2654435761u;
        unsigned hz0 = uz * 805459861u,  hz1 = (uz + 1u) * 805459861u;
        float wx0 = 1.0f - wx, wy0 = 1.0f - wy, wz0 = 1.0f - wz;
        const float4* tl = tables4 + ((size_t)l << 16);
        float ax = 0.0f, ay = 0.0f, az = 0.0f, aw = 0.0f;
        {
            float4 c = __ldg(tl + ((ux  ^ hy0 ^ hz0) & 0xFFFFu)); float w = wx0 * wy0 * wz0;
            ax = fmaf(w, c.x, ax); ay = fmaf(w, c.y, ay); az = fmaf(w, c.z, az); aw = fmaf(w, c.w, aw);
        }
        {
            float4 c = __ldg(tl + ((ux  ^ hy0 ^ hz1) & 0xFFFFu)); float w = wx0 * wy0 * wz;
            ax = fmaf(w, c.x, ax); ay = fmaf(w, c.y, ay); az = fmaf(w, c.z, az); aw = fmaf(w, c.w, aw);
        }
        {
            float4 c = __ldg(tl + ((ux  ^ hy1 ^ hz0) & 0xFFFFu)); float w = wx0 * wy * wz0;
            ax = fmaf(w, c.x, ax); ay = fmaf(w, c.y, ay); az = fmaf(w, c.z, az); aw = fmaf(w, c.w, aw);
        }
        {
            float4 c = __ldg(tl + ((ux  ^ hy1 ^ hz1) & 0xFFFFu)); float w = wx0 * wy * wz;
            ax = fmaf(w, c.x, ax); ay = fmaf(w, c.y, ay); az = fmaf(w, c.z, az); aw = fmaf(w, c.w, aw);
        }
        {
            float4 c = __ldg(tl + ((ux1 ^ hy0 ^ hz0) & 0xFFFFu)); float w = wx * wy0 * wz0;
            ax = fmaf(w, c.x, ax); ay = fmaf(w, c.y, ay); az = fmaf(w, c.z, az); aw = fmaf(w, c.w, aw);
        }
        {
            float4 c = __ldg(tl + ((ux1 ^ hy0 ^ hz1) & 0xFFFFu)); float w = wx * wy0 * wz;
            ax = fmaf(w, c.x, ax); ay = fmaf(w, c.y, ay); az = fmaf(w, c.z, az); aw = fmaf(w, c.w, aw);
        }
        {
            float4 c = __ldg(tl + ((ux1 ^ hy1 ^ hz0) & 0xFFFFu)); float w = wx * wy * wz0;
            ax = fmaf(w, c.x, ax); ay = fmaf(w, c.y, ay); az = fmaf(w, c.z, az); aw = fmaf(w, c.w, aw);
        }
        {
            float4 c = __ldg(tl + ((ux1 ^ hy1 ^ hz1) & 0xFFFFu)); float w = wx * wy * wz;
            ax = fmaf(w, c.x, ax); ay = fmaf(w, c.y, ay); az = fmaf(w, c.z, az); aw = fmaf(w, c.w, aw);
        }
        float denom = 8.0f * (float)l * cr;
        float sc = erff(rsqrtf(fmaxf(denom, EPSF)));
        xin[l]      = ax * sc;
        xin[10 + l] = ay * sc;
        xin[20 + l] = az * sc;
        xin[30 + l] = aw * sc;
    }

    // ---------------- layer 1: 40 -> 64, weights from constant ----------------
    float h1[64];
#pragma unroll
    for (int c = 0; c < 4; ++c) {
        float acc[16];
#pragma unroll
        for (int j = 0; j < 16; ++j) acc[j] = cB1[c * 16 + j];
#pragma unroll
        for (int i = 0; i < 40; ++i) {
#pragma unroll
            for (int j = 0; j < 16; ++j)
                acc[j] = fmaf(xin[i], cW1[i * 64 + c * 16 + j], acc[j]);
        }
#pragma unroll
        for (int j = 0; j < 16; ++j) h1[c * 16 + j] = seluf(acc[j]);
    }

    // ---------------- layer 2 (64->64) fused with layer 3 (64->16) ----------------
    float oacc[16];
#pragma unroll
    for (int j = 0; j < 16; ++j) oacc[j] = cB3[j];

#pragma unroll
    for (int c = 0; c < 8; ++c) {
        float acc[8];
#pragma unroll
        for (int j = 0; j < 8; ++j) acc[j] = cB2[c * 8 + j];
#pragma unroll
        for (int i = 0; i < 64; ++i) {
#pragma unroll
            for (int j = 0; j < 8; ++j)
                acc[j] = fmaf(h1[i], cW2[i * 64 + c * 8 + j], acc[j]);
        }
        float h2v[8];
#pragma unroll
        for (int j = 0; j < 8; ++j) h2v[j] = seluf(acc[j]);
#pragma unroll
        for (int k = 0; k < 8; ++k) {
#pragma unroll
            for (int j = 0; j < 16; ++j)
                oacc[j] = fmaf(h2v[k], cW3[(c * 8 + k) * 16 + j], oacc[j]);
        }
    }

    // ---------------- lighting epilogue ----------------
    float out0 = softplusf(oacc[0]);
    float out1 = softplusf(oacc[1]);
    float out2 = softplusf(oacc[2]);

#pragma unroll
    for (int k = 0; k < 2; ++k) {
        const int b = 4 + 6 * k;
        float lc0 = softplusf(oacc[b + 0] - 3.0f);
        float lc1 = softplusf(oacc[b + 1] - 3.0f);
        float lc2 = softplusf(oacc[b + 2] - 3.0f);
        float e = oacc[b + 3] - 1.0f;
        e = fminf(fmaxf(e, -30.0f), 15.0f);
        float rough = 4.0f * fminf(expf(e), 100.0f);
        float rd0 = oacc[b + 4] + (k ? 3.14159265358979323846f : 0.0f);
        float rd1 = oacc[b + 5];
        float s0, c0, s1, c1;
        sincosf(rd0, &s0, &c0);
        sincosf(rd1, &s1, &c1);
        float rx = c0 * s1, ry = s0 * s1, rz = c1;
        float sim = rx * vdx + ry * vdy + rz * vdz;
        float spec = (sim > 0.0f) ? powf(fmaxf(sim, EPSF), rough) : 0.0f;
        out0 = fmaf(lc0, spec, out0);
        out1 = fmaf(lc1, spec, out1);
        out2 = fmaf(lc2, spec, out2);
    }

    outp[3 * t + 0] = out0;
    outp[3 * t + 1] = out1;
    outp[3 * t + 2] = out2;
}

extern "C" void kernel_launch(void* const* d_in, const int* in_sizes, int n_in,
                              void* d_out, int out_size)
{
    const float*  vertices = (const float*)d_in[0];
    const int4*   indices  = (const int4*)d_in[1];
    const float*  camera   = (const float*)d_in[2];
    const float4* tables   = (const float4*)d_in[3];
    const float*  center   = (const float*)d_in[10];
    const float*  scale    = (const float*)d_in[11];

    // Upload MLP weights to constant memory (D2D async copies — graph-capturable)
    cudaMemcpyToSymbolAsync(cW1, d_in[4], 40 * 64 * sizeof(float), 0, cudaMemcpyDeviceToDevice, 0);
    cudaMemcpyToSymbolAsync(cB1, d_in[5], 64 * sizeof(float),      0, cudaMemcpyDeviceToDevice, 0);
    cudaMemcpyToSymbolAsync(cW2, d_in[6], 64 * 64 * sizeof(float), 0, cudaMemcpyDeviceToDevice, 0);
    cudaMemcpyToSymbolAsync(cB2, d_in[7], 64 * sizeof(float),      0, cudaMemcpyDeviceToDevice, 0);
    cudaMemcpyToSymbolAsync(cW3, d_in[8], 64 * 16 * sizeof(float), 0, cudaMemcpyDeviceToDevice, 0);
    cudaMemcpyToSymbolAsync(cB3, d_in[9], 16 * sizeof(float),      0, cudaMemcpyDeviceToDevice, 0);

    int T = in_sizes[1] / 4;
    int grid = (T + NTHREADS - 1) / NTHREADS;
    tetshade_kernel<<<grid, NTHREADS>>>(vertices, indices, camera, tables,
                                        (float*)d_out, center, scale, T);
}

// round 4
// speedup vs baseline: 1.9407x; 1.0511x over previous
#include <cuda_runtime.h>
#include <math.h>

#define NTHREADS 128

__constant__ float cW1[40 * 64];
__constant__ float cB1[64];
__constant__ float cW2[64 * 64];
__constant__ float cB2[64];
__constant__ float cW3[64 * 16];
__constant__ float cB3[16];

static __device__ __forceinline__ float seluf(float x) {
    const float lam    = 1.0507009873554805f;
    const float lamalp = 1.7580993408473766f;   // lam * alpha
    float e = __expf(x) - 1.0f;
    return x > 0.0f ? lam * x : lamalp * e;
}

static __device__ __forceinline__ float softplusf(float x) {
    return fmaxf(x, 0.0f) + log1pf(expf(-fabsf(x)));
}

__global__ void __launch_bounds__(NTHREADS, 5)
tetshade_kernel(
    const float*  __restrict__ vertices,   // (V,3)
    const int4*   __restrict__ indices,    // (T,4)
    const float*  __restrict__ camera,     // (3,)
    const float4* __restrict__ tables4,    // (L, 65536, 4)
    float*        __restrict__ outp,       // (T,3)
    const float*  __restrict__ centerp,
    const float*  __restrict__ scalep,
    int T)
{
    int t = blockIdx.x * NTHREADS + threadIdx.x;
    if (t >= T) return;

    const float EPSF = 1.1920928955078125e-07f;

    // ---------------- gather tet vertices ----------------
    int4 id = indices[t];
    float v0x = __ldg(vertices + 3 * id.x + 0);
    float v0y = __ldg(vertices + 3 * id.x + 1);
    float v0z = __ldg(vertices + 3 * id.x + 2);
    float v1x = __ldg(vertices + 3 * id.y + 0);
    float v1y = __ldg(vertices + 3 * id.y + 1);
    float v1z = __ldg(vertices + 3 * id.y + 2);
    float v2x = __ldg(vertices + 3 * id.z + 0);
    float v2y = __ldg(vertices + 3 * id.z + 1);
    float v2z = __ldg(vertices + 3 * id.z + 2);
    float v3x = __ldg(vertices + 3 * id.w + 0);
    float v3y = __ldg(vertices + 3 * id.w + 1);
    float v3z = __ldg(vertices + 3 * id.w + 2);

    // view direction from barycenter
    float bx = 0.25f * (v0x + v1x + v2x + v3x);
    float by = 0.25f * (v0y + v1y + v2y + v3y);
    float bz = 0.25f * (v0z + v1z + v2z + v3z);
    float vdx = __ldg(camera + 0) - bx;
    float vdy = __ldg(camera + 1) - by;
    float vdz = __ldg(camera + 2) - bz;
    {
        float vn = fmaxf(sqrtf(vdx * vdx + vdy * vdy + vdz * vdz), EPSF);
        vdx /= vn; vdy /= vn; vdz /= vn;
    }

    // ---------------- circumcenter solve ----------------
    float a00 = 2.0f * (v1x - v0x) + 1e-6f;
    float a01 = 2.0f * (v1y - v0y);
    float a02 = 2.0f * (v1z - v0z);
    float a10 = 2.0f * (v2x - v0x);
    float a11 = 2.0f * (v2y - v0y) + 1e-6f;
    float a12 = 2.0f * (v2z - v0z);
    float a20 = 2.0f * (v3x - v0x);
    float a21 = 2.0f * (v3y - v0y);
    float a22 = 2.0f * (v3z - v0z) + 1e-6f;
    float r0 = (v1x * v1x - v0x * v0x) + (v1y * v1y - v0y * v0y) + (v1z * v1z - v0z * v0z);
    float r1 = (v2x * v2x - v0x * v0x) + (v2y * v2y - v0y * v0y) + (v2z * v2z - v0z * v0z);
    float r2 = (v3x * v3x - v0x * v0x) + (v3y * v3y - v0y * v0y) + (v3z * v3z - v0z * v0z);
    {
        float tmp;
        float m0 = fabsf(a00), m1a = fabsf(a10), m2a = fabsf(a20);
        if (m1a > m0 && m1a >= m2a) {
            tmp = a00; a00 = a10; a10 = tmp;
            tmp = a01; a01 = a11; a11 = tmp;
            tmp = a02; a02 = a12; a12 = tmp;
            tmp = r0;  r0  = r1;  r1  = tmp;
        } else if (m2a > m0) {
            tmp = a00; a00 = a20; a20 = tmp;
            tmp = a01; a01 = a21; a21 = tmp;
            tmp = a02; a02 = a22; a22 = tmp;
            tmp = r0;  r0  = r2;  r2  = tmp;
        }
        float f1 = a10 / a00, f2 = a20 / a00;
        a11 -= f1 * a01; a12 -= f1 * a02; r1 -= f1 * r0;
        a21 -= f2 * a01; a22 -= f2 * a02; r2 -= f2 * r0;
        if (fabsf(a21) > fabsf(a11)) {
            tmp = a11; a11 = a21; a21 = tmp;
            tmp = a12; a12 = a22; a22 = tmp;
            tmp = r1;  r1  = r2;  r2  = tmp;
        }
        float f3 = a21 / a11;
        a22 -= f3 * a12; r2 -= f3 * r1;
    }
    float ccz = r2 / a22;
    float ccy = (r1 - a12 * ccz) / a11;
    float ccx = (r0 - a01 * ccy - a02 * ccz) / a00;

    float radius = sqrtf((ccx - v0x) * (ccx - v0x) +
                         (ccy - v0y) * (ccy - v0y) +
                         (ccz - v0z) * (ccz - v0z));

    // ---------------- ball contraction ----------------
    float ss  = __ldg(scalep);
    float nx  = (ccx - __ldg(centerp + 0)) / ss;
    float ny  = (ccy - __ldg(centerp + 1)) / ss;
    float nz  = (ccz - __ldg(centerp + 2)) / ss;
    float n   = fmaxf(sqrtf(nx * nx + ny * ny + nz * nz), EPSF);
    float cvx, cvy, cvz, fac;
    if (n <= 1.0f) {
        cvx = nx; cvy = ny; cvz = nz; fac = 1.0f;
    } else {
        float inv = 1.0f / n;
        float s2  = (2.0f - inv) * inv;
        cvx = nx * s2; cvy = ny * s2; cvz = nz * s2;
        fac = inv * inv;
    }
    float cr = radius / ss * fac * 0.5f;

    float hx = cvx * 0.25f + 0.5f;
    float hy = cvy * 0.25f + 0.5f;
    float hz = cvz * 0.25f + 0.5f;

    // ---------------- hash-grid encode fused with layer 1 ----------------
    // h1acc[j] accumulates sum_i xin[i] * W1[i][j]; per level i = {l, 10+l, 20+l, 30+l}
    float h1acc[64];
#pragma unroll
    for (int j = 0; j < 64; ++j) h1acc[j] = cB1[j];

#pragma unroll
    for (int l = 0; l < 10; ++l) {
        float resf = (float)(16 << l);
        float px = hx * resf, py = hy * resf, pz = hz * resf;
        float fx = floorf(px), fy = floorf(py), fz = floorf(pz);
        float wx = px - fx, wy = py - fy, wz = pz - fz;
        unsigned ux = (unsigned)(int)fx;
        unsigned uy = (unsigned)(int)fy;
        unsigned uz = (unsigned)(int)fz;
        unsigned ux1 = ux + 1u;
        unsigned hy0 = uy * 2654435761u, hy1 = (uy + 1u) * 2654435761u;
        unsigned hz0 = uz * 805459861u,  hz1 = (uz + 1u) * 805459861u;
        float wx0 = 1.0f - wx, wy0 = 1.0f - wy, wz0 = 1.0f - wz;
        const float4* tl = tables4 + ((size_t)l << 16);

        float4 c0 = __ldg(tl + ((ux  ^ hy0 ^ hz0) & 0xFFFFu));
        float4 c1 = __ldg(tl + ((ux  ^ hy0 ^ hz1) & 0xFFFFu));
        float4 c2 = __ldg(tl + ((ux  ^ hy1 ^ hz0) & 0xFFFFu));
        float4 c3 = __ldg(tl + ((ux  ^ hy1 ^ hz1) & 0xFFFFu));
        float4 c4 = __ldg(tl + ((ux1 ^ hy0 ^ hz0) & 0xFFFFu));
        float4 c5 = __ldg(tl + ((ux1 ^ hy0 ^ hz1) & 0xFFFFu));
        float4 c6 = __ldg(tl + ((ux1 ^ hy1 ^ hz0) & 0xFFFFu));
        float4 c7 = __ldg(tl + ((ux1 ^ hy1 ^ hz1) & 0xFFFFu));

        float w0 = wx0 * wy0 * wz0;
        float w1 = wx0 * wy0 * wz;
        float w2 = wx0 * wy  * wz0;
        float w3 = wx0 * wy  * wz;
        float w4 = wx  * wy0 * wz0;
        float w5 = wx  * wy0 * wz;
        float w6 = wx  * wy  * wz0;
        float w7 = wx  * wy  * wz;

        float ax = w0 * c0.x, ay = w0 * c0.y, az = w0 * c0.z, aw = w0 * c0.w;
        ax = fmaf(w1, c1.x, ax); ay = fmaf(w1, c1.y, ay); az = fmaf(w1, c1.z, az); aw = fmaf(w1, c1.w, aw);
        ax = fmaf(w2, c2.x, ax); ay = fmaf(w2, c2.y, ay); az = fmaf(w2, c2.z, az); aw = fmaf(w2, c2.w, aw);
        ax = fmaf(w3, c3.x, ax); ay = fmaf(w3, c3.y, ay); az = fmaf(w3, c3.z, az); aw = fmaf(w3, c3.w, aw);
        ax = fmaf(w4, c4.x, ax); ay = fmaf(w4, c4.y, ay); az = fmaf(w4, c4.z, az); aw = fmaf(w4, c4.w, aw);
        ax = fmaf(w5, c5.x, ax); ay = fmaf(w5, c5.y, ay); az = fmaf(w5, c5.z, az); aw = fmaf(w5, c5.w, aw);
        ax = fmaf(w6, c6.x, ax); ay = fmaf(w6, c6.y, ay); az = fmaf(w6, c6.z, az); aw = fmaf(w6, c6.w, aw);
        ax = fmaf(w7, c7.x, ax); ay = fmaf(w7, c7.y, ay); az = fmaf(w7, c7.z, az); aw = fmaf(w7, c7.w, aw);

        float denom = 8.0f * (float)l * cr;
        float sc = erff(rsqrtf(fmaxf(denom, EPSF)));
        float f0 = ax * sc;     // xin[l]        -> W1 row  l
        float f1 = ay * sc;     // xin[10 + l]   -> W1 row 10+l
        float f2 = az * sc;     // xin[20 + l]   -> W1 row 20+l
        float f3 = aw * sc;     // xin[30 + l]   -> W1 row 30+l

        const float* wr0 = &cW1[(l)      * 64];
        const float* wr1 = &cW1[(10 + l) * 64];
        const float* wr2 = &cW1[(20 + l) * 64];
        const float* wr3 = &cW1[(30 + l) * 64];
#pragma unroll
        for (int j = 0; j < 64; ++j) {
            float a = h1acc[j];
            a = fmaf(f0, wr0[j], a);
            a = fmaf(f1, wr1[j], a);
            a = fmaf(f2, wr2[j], a);
            a = fmaf(f3, wr3[j], a);
            h1acc[j] = a;
        }
    }

    // selu (in place)
#pragma unroll
    for (int j = 0; j < 64; ++j) h1acc[j] = seluf(h1acc[j]);

    // ---------------- layer 2 (64->64) fused with layer 3 (64->16) ----------------
    float oacc[16];
#pragma unroll
    for (int j = 0; j < 16; ++j) oacc[j] = cB3[j];

#pragma unroll
    for (int c = 0; c < 8; ++c) {
        float acc[8];
#pragma unroll
        for (int j = 0; j < 8; ++j) acc[j] = cB2[c * 8 + j];
#pragma unroll
        for (int i = 0; i < 64; ++i) {
#pragma unroll
            for (int j = 0; j < 8; ++j)
                acc[j] = fmaf(h1acc[i], cW2[i * 64 + c * 8 + j], acc[j]);
        }
        float h2v[8];
#pragma unroll
        for (int j = 0; j < 8; ++j) h2v[j] = seluf(acc[j]);
#pragma unroll
        for (int k = 0; k < 8; ++k) {
#pragma unroll
            for (int j = 0; j < 16; ++j)
                oacc[j] = fmaf(h2v[k], cW3[(c * 8 + k) * 16 + j], oacc[j]);
        }
    }

    // ---------------- lighting epilogue ----------------
    float out0 = softplusf(oacc[0]);
    float out1 = softplusf(oacc[1]);
    float out2 = softplusf(oacc[2]);

#pragma unroll
    for (int k = 0; k < 2; ++k) {
        const int b = 4 + 6 * k;
        float lc0 = softplusf(oacc[b + 0] - 3.0f);
        float lc1 = softplusf(oacc[b + 1] - 3.0f);
        float lc2 = softplusf(oacc[b + 2] - 3.0f);
        float e = oacc[b + 3] - 1.0f;
        e = fminf(fmaxf(e, -30.0f), 15.0f);
        float rough = 4.0f * fminf(expf(e), 100.0f);
        float rd0 = oacc[b + 4] + (k ? 3.14159265358979323846f : 0.0f);
        float rd1 = oacc[b + 5];
        float s0, c0, s1, c1;
        sincosf(rd0, &s0, &c0);
        sincosf(rd1, &s1, &c1);
        float rx = c0 * s1, ry = s0 * s1, rz = c1;
        float sim = rx * vdx + ry * vdy + rz * vdz;
        float spec = (sim > 0.0f) ? powf(fmaxf(sim, EPSF), rough) : 0.0f;
        out0 = fmaf(lc0, spec, out0);
        out1 = fmaf(lc1, spec, out1);
        out2 = fmaf(lc2, spec, out2);
    }

    outp[3 * t + 0] = out0;
    outp[3 * t + 1] = out1;
    outp[3 * t + 2] = out2;
}

extern "C" void kernel_launch(void* const* d_in, const int* in_sizes, int n_in,
                              void* d_out, int out_size)
{
    const float*  vertices = (const float*)d_in[0];
    const int4*   indices  = (const int4*)d_in[1];
    const float*  camera   = (const float*)d_in[2];
    const float4* tables   = (const float4*)d_in[3];
    const float*  center   = (const float*)d_in[10];
    const float*  scale    = (const float*)d_in[11];

    // Upload MLP weights to constant memory (D2D async copies — graph-capturable)
    cudaMemcpyToSymbolAsync(cW1, d_in[4], 40 * 64 * sizeof(float), 0, cudaMemcpyDeviceToDevice, 0);
    cudaMemcpyToSymbolAsync(cB1, d_in[5], 64 * sizeof(float),      0, cudaMemcpyDeviceToDevice, 0);
    cudaMemcpyToSymbolAsync(cW2, d_in[6], 64 * 64 * sizeof(float), 0, cudaMemcpyDeviceToDevice, 0);
    cudaMemcpyToSymbolAsync(cB2, d_in[7], 64 * sizeof(float),      0, cudaMemcpyDeviceToDevice, 0);
    cudaMemcpyToSymbolAsync(cW3, d_in[8], 64 * 16 * sizeof(float), 0, cudaMemcpyDeviceToDevice, 0);
    cudaMemcpyToSymbolAsync(cB3, d_in[9], 16 * sizeof(float),      0, cudaMemcpyDeviceToDevice, 0);

    int T = in_sizes[1] / 4;
    int grid = (T + NTHREADS - 1) / NTHREADS;
    tetshade_kernel<<<grid, NTHREADS>>>(vertices, indices, camera, tables,
                                        (float*)d_out, center, scale, T);
}